// round 17
// baseline (speedup 1.0000x reference)
#include <cuda_runtime.h>
#include <cuda_fp16.h>
#include <cuda_bf16.h>

// Problem constants (fixed shapes per reference)
#define Nn   100000
#define Ee   1600000
#define FIN  128
#define FHID 32
#define FOUT 2

// ---------------- scratch (__device__ globals; no allocation) ----------------
// g_cnt relies on zero-init at module load; k_final re-zeroes it every call.
__device__ __align__(16) __half g_g1h[Nn * FHID];   // dinv-scaled h1 (fp16)   6.4 MB
__device__ __align__(16) __half g_agg1h[Nn * FHID]; // layer-1 accum (fp16)    6.4 MB
__device__ __align__(8)  float g_g2[Nn * FOUT];     // dinv-scaled h2          0.8 MB
__device__ __align__(8)  float g_agg2[Nn * FOUT];   // layer-2 accum           0.8 MB
__device__ int g_cnt[Nn];                            // in-degree (no self loop)

// ---------------- kernels ----------------

// degree histogram: 4 independent int4 loads per thread (MLP=4), 16 REDs
__global__ void k_hist(const int* __restrict__ ei) {
    const int N = Ee / 16;                       // 100000 threads, 4 strips
    int t = blockIdx.x * blockDim.x + threadIdx.x;
    if (t >= N) return;
    const int4* c4 = reinterpret_cast<const int4*>(ei + Ee);
    int4 a = c4[t];
    int4 b = c4[t + N];
    int4 c = c4[t + 2 * N];
    int4 d = c4[t + 3 * N];
    atomicAdd(&g_cnt[a.x], 1); atomicAdd(&g_cnt[a.y], 1);
    atomicAdd(&g_cnt[a.z], 1); atomicAdd(&g_cnt[a.w], 1);
    atomicAdd(&g_cnt[b.x], 1); atomicAdd(&g_cnt[b.y], 1);
    atomicAdd(&g_cnt[b.z], 1); atomicAdd(&g_cnt[b.w], 1);
    atomicAdd(&g_cnt[c.x], 1); atomicAdd(&g_cnt[c.y], 1);
    atomicAdd(&g_cnt[c.z], 1); atomicAdd(&g_cnt[c.w], 1);
    atomicAdd(&g_cnt[d.x], 1); atomicAdd(&g_cnt[d.y], 1);
    atomicAdd(&g_cnt[d.z], 1); atomicAdd(&g_cnt[d.w], 1);
}

// g1 = dinv * (x @ W1) via packed fma.rn.f32x2; 8 nodes/warp, 64 nodes/block.
// Stores PRESCALED fp16 g1 and initializes agg1 with the self-loop term. (proven R9/R15)
__global__ void __launch_bounds__(256) k_gemm1(const float* __restrict__ x,
                                               const float* __restrict__ W1) {
    __shared__ __align__(16) float sWp[FIN * FHID]; // paired: u64[p*32+lane]={W[2p],W[2p+1]}  16 KB
    __shared__ __align__(16) float sx[64 * FIN];    // 64 x-rows                               32 KB
    int tid = threadIdx.x;
    for (int i = tid; i < FIN * FHID; i += 256) {
        int k = i >> 5, lane = i & 31;
        sWp[(((k >> 1) * 32) + lane) * 2 + (k & 1)] = W1[i];
    }
    int nodeBase = blockIdx.x * 64;
    {
        const float4* x4 = reinterpret_cast<const float4*>(x);
        float4* sx4 = reinterpret_cast<float4*>(sx);
        for (int i = tid; i < 2048; i += 256) {
            int node = nodeBase + (i >> 5);
            sx4[i] = (node < Nn) ? x4[(size_t)node * 32 + (i & 31)]
                                 : make_float4(0.f, 0.f, 0.f, 0.f);
        }
    }
    __syncthreads();

    int w = tid >> 5, lane = tid & 31;
    int n0 = w * 8;                                   // local node base
    const ulonglong2* sxq = reinterpret_cast<const ulonglong2*>(sx);      // 32 per 128-float row
    const unsigned long long* sWq = reinterpret_cast<const unsigned long long*>(sWp);

    unsigned long long acc[8];
#pragma unroll
    for (int i = 0; i < 8; i++) acc[i] = 0ULL;        // {0.f, 0.f}

#pragma unroll
    for (int kp2 = 0; kp2 < 32; kp2++) {              // covers k = 4*kp2 .. 4*kp2+3
        unsigned long long w0 = sWq[(2 * kp2 + 0) * 32 + lane];
        unsigned long long w1 = sWq[(2 * kp2 + 1) * 32 + lane];
#pragma unroll
        for (int i = 0; i < 8; i++) {
            ulonglong2 xv = sxq[(n0 + i) * 32 + kp2]; // row stride = 32 ulonglong2
            asm("fma.rn.f32x2 %0, %1, %2, %0;" : "+l"(acc[i]) : "l"(xv.x), "l"(w0));
            asm("fma.rn.f32x2 %0, %1, %2, %0;" : "+l"(acc[i]) : "l"(xv.y), "l"(w1));
        }
    }

#pragma unroll
    for (int i = 0; i < 8; i++) {
        int gn = nodeBase + n0 + i;
        if (gn < Nn) {
            float lo, hi;
            asm("mov.b64 {%0,%1}, %2;" : "=f"(lo), "=f"(hi) : "l"(acc[i]));
            float dinv = rsqrtf((float)g_cnt[gn] + 1.0f);
            __half h = __float2half_rn(dinv * (lo + hi));
            g_g1h  [gn * FHID + lane] = h;
            g_agg1h[gn * FHID + lane] = h;            // self-loop init
        }
    }
}

// layer-1 edge scatter (fp16): ONE THREAD PER EDGE.
// 2 idx loads + 4 independent LDG.128 row loads + 4 v4.f16x2 REDs = 10 LSU ops/edge
// (vs 20 for the 4-lane layout; scatter1 is LSU-issue bound at ~4 ops/cyc/SM).
__global__ void k_scatter1(const int* __restrict__ ei) {
    int e = blockIdx.x * blockDim.x + threadIdx.x;
    if (e >= Ee) return;
    int r = ei[e];
    int c = ei[Ee + e];
    const uint4* src = reinterpret_cast<const uint4*>(g_g1h) + r * 4;
    uint4 v0 = src[0];                       // 4 independent 16B loads (MLP=4)
    uint4 v1 = src[1];
    uint4 v2 = src[2];
    uint4 v3 = src[3];
    __half* dst = g_agg1h + c * FHID;
    asm volatile("red.global.add.noftz.v4.f16x2 [%0], {%1,%2,%3,%4};"
                 :: "l"(dst +  0), "r"(v0.x), "r"(v0.y), "r"(v0.z), "r"(v0.w) : "memory");
    asm volatile("red.global.add.noftz.v4.f16x2 [%0], {%1,%2,%3,%4};"
                 :: "l"(dst +  8), "r"(v1.x), "r"(v1.y), "r"(v1.z), "r"(v1.w) : "memory");
    asm volatile("red.global.add.noftz.v4.f16x2 [%0], {%1,%2,%3,%4};"
                 :: "l"(dst + 16), "r"(v2.x), "r"(v2.y), "r"(v2.z), "r"(v2.w) : "memory");
    asm volatile("red.global.add.noftz.v4.f16x2 [%0], {%1,%2,%3,%4};"
                 :: "l"(dst + 24), "r"(v3.x), "r"(v3.y), "r"(v3.z), "r"(v3.w) : "memory");
}

// a1 = relu(dinv*agg1 + b1); g2 = dinv*(a1 @ W2); agg2 init = g2 (self loop)
// thread per node: 4x LDG.128 row read, 64 FMAs, W2/b1 via smem broadcast (proven R10/R15)
__global__ void __launch_bounds__(256) k_layer2(const float* __restrict__ b1,
                                                const float* __restrict__ W2) {
    __shared__ float sW[FHID * FOUT];   // 64 floats
    __shared__ float sb[FHID];          // 32 floats
    int tid = threadIdx.x;
    if (tid < FHID * FOUT) sW[tid] = W2[tid];
    if (tid < FHID)        sb[tid] = b1[tid];
    __syncthreads();

    int n = blockIdx.x * 256 + tid;
    if (n >= Nn) return;
    float dinv = rsqrtf((float)g_cnt[n] + 1.0f);
    const uint4* row = reinterpret_cast<const uint4*>(g_agg1h) + n * 4;
    float p0 = 0.f, p1 = 0.f;
#pragma unroll
    for (int q = 0; q < 4; q++) {
        uint4 v = row[q];
        unsigned u[4] = {v.x, v.y, v.z, v.w};
#pragma unroll
        for (int h = 0; h < 4; h++) {
            float2 f = __half22float2(*reinterpret_cast<const __half2*>(&u[h]));
            int k = q * 8 + h * 2;
            float a0 = fmaxf(fmaf(dinv, f.x, sb[k + 0]), 0.f);
            float a1 = fmaxf(fmaf(dinv, f.y, sb[k + 1]), 0.f);
            p0 = fmaf(a0, sW[2 * k + 0], fmaf(a1, sW[2 * k + 2], p0));
            p1 = fmaf(a0, sW[2 * k + 1], fmaf(a1, sW[2 * k + 3], p1));
        }
    }
    float2 g = make_float2(dinv * p0, dinv * p1);
    reinterpret_cast<float2*>(g_g2)[n]   = g;
    reinterpret_cast<float2*>(g_agg2)[n] = g;   // self-loop init
}

// layer-2 edge scatter: 4 edges/thread (int4 indices, 4 independent gathers)
__global__ void k_scatter2(const int* __restrict__ ei) {
    int t = blockIdx.x * blockDim.x + threadIdx.x;
    if (t >= Ee / 4) return;
    int4 r = reinterpret_cast<const int4*>(ei)[t];
    int4 c = reinterpret_cast<const int4*>(ei + Ee)[t];
    float2 v0 = reinterpret_cast<const float2*>(g_g2)[r.x];
    float2 v1 = reinterpret_cast<const float2*>(g_g2)[r.y];
    float2 v2 = reinterpret_cast<const float2*>(g_g2)[r.z];
    float2 v3 = reinterpret_cast<const float2*>(g_g2)[r.w];
    atomicAdd(reinterpret_cast<float2*>(g_agg2) + c.x, v0);
    atomicAdd(reinterpret_cast<float2*>(g_agg2) + c.y, v1);
    atomicAdd(reinterpret_cast<float2*>(g_agg2) + c.z, v2);
    atomicAdd(reinterpret_cast<float2*>(g_agg2) + c.w, v3);
}

// finalize: o = dinv*agg2 + b2; log_softmax; then reset g_cnt for next call
__global__ void k_final(const float* __restrict__ b2, float* __restrict__ out) {
    int n = blockIdx.x * blockDim.x + threadIdx.x;
    if (n >= Nn) return;
    float dinv = rsqrtf((float)g_cnt[n] + 1.0f);
    float2 s = reinterpret_cast<const float2*>(g_agg2)[n];
    float o0 = dinv * s.x + b2[0];
    float o1 = dinv * s.y + b2[1];
    float m = fmaxf(o0, o1);
    float lse = m + logf(expf(o0 - m) + expf(o1 - m));
    reinterpret_cast<float2*>(out)[n] = make_float2(o0 - lse, o1 - lse);
    g_cnt[n] = 0;                       // restore zero invariant for next call
}

// ---------------- launch ----------------
extern "C" void kernel_launch(void* const* d_in, const int* in_sizes, int n_in,
                              void* d_out, int out_size) {
    const float* x  = (const float*)d_in[0];
    const int*   ei = (const int*)d_in[1];   // int32 on the wire
    const float* W1 = (const float*)d_in[2];
    const float* b1 = (const float*)d_in[3];
    const float* W2 = (const float*)d_in[4];
    const float* b2 = (const float*)d_in[5];
    float* out = (float*)d_out;

    const int T = 256;
    k_hist    <<<(Ee / 16 + T - 1) / T, T>>>(ei);
    k_gemm1   <<<(Nn + 63) / 64, T>>>(x, W1);
    k_scatter1<<<(Ee + T - 1) / T, T>>>(ei);
    k_layer2  <<<(Nn + T - 1) / T, T>>>(b1, W2);
    k_scatter2<<<(Ee / 4 + T - 1) / T, T>>>(ei);
    k_final   <<<(Nn + T - 1) / T, T>>>(b2, out);
}